// round 8
// baseline (speedup 1.0000x reference)
#include <cuda_runtime.h>
#include <cuda_bf16.h>
#include <cstdint>
#include <cstddef>

// ---------------------------------------------------------------------------
// GroupedKNNEstimator: out[q] = mean_k ( (sqrt(knn_d2_k) - min) / (max - min) )
// N=2048 queries, M=100000 bank rows, D=128, K=5.
// R7: int8 mma.m16n8k32 screening (2x MACs/instr vs bf16 m16n8k16) tracking
// candidate indices; merge recomputes exact fp32 d2 for the 90 survivors per
// query and selects the true top-5. Output is fp32-exact.
// ---------------------------------------------------------------------------

#define D_DIM   128
#define QB      128          // queries per CTA (CTA tile M)
#define CB      128          // candidates per tile (CTA tile N)
#define NSPLIT  9            // M-dimension splits (grid.y)
#define KNN     5
#define MAXN    2048
#define MAXROWS 100096       // M padded to CB multiple (782*128)
#define PARTS   (NSPLIT * 2) // partial top-5 lists per query (2 per CTA)
#define PSTRIDE (PARTS * KNN)// 90 candidates per query

#define SCALE   24.0f
#define NEG2IS2 (-2.0f / (SCALE * SCALE))

#define ASTRIDE 144          // padded row stride (bytes) for 128 int8 rows

// SMEM layout: A tile + 3 B buffers (B tile + y2 vector each)
#define SMEM_A     0
#define A_BYTES    (QB * ASTRIDE)          // 18432
#define BUF_BYTES  (CB * ASTRIDE + 512)    // 18944 (B + 128 y2 floats)
#define BBUF(i)    (A_BYTES + (i) * BUF_BYTES)
#define SMEM_TOTAL (A_BYTES + 3 * BUF_BYTES)   // 75264

__device__ uint8_t g_bank_i8[(size_t)MAXROWS * D_DIM];
__device__ float g_y2[MAXROWS];
__device__ int g_pidx[(size_t)MAXN * PSTRIDE];   // [q][90] candidate indices

static __device__ __forceinline__ uint32_t smem_u32(const void* p) {
    uint32_t a;
    asm("{ .reg .u64 t; cvta.to.shared.u64 t, %1; cvt.u32.u64 %0, t; }"
        : "=r"(a) : "l"(p));
    return a;
}

static __device__ __forceinline__ void cp_async16(uint32_t dst, const void* src) {
    asm volatile("cp.async.cg.shared.global [%0], [%1], 16;" :: "r"(dst), "l"(src));
}
static __device__ __forceinline__ void cp_commit() {
    asm volatile("cp.async.commit_group;" ::: "memory");
}
template <int NN>
static __device__ __forceinline__ void cp_wait() {
    asm volatile("cp.async.wait_group %0;" :: "n"(NN) : "memory");
}

static __device__ __forceinline__ void imma_16832(int (&c)[4],
                                                  uint32_t a0, uint32_t a1,
                                                  uint32_t a2, uint32_t a3,
                                                  uint32_t b0, uint32_t b1) {
    asm volatile(
        "mma.sync.aligned.m16n8k32.row.col.s32.s8.s8.s32 "
        "{%0,%1,%2,%3}, {%4,%5,%6,%7}, {%8,%9}, {%0,%1,%2,%3};"
        : "+r"(c[0]), "+r"(c[1]), "+r"(c[2]), "+r"(c[3])
        : "r"(a0), "r"(a1), "r"(a2), "r"(a3), "r"(b0), "r"(b1));
}

static __device__ __forceinline__ void top5_update_i(float (&t)[5], int (&ti)[5],
                                                     float s, int idx) {
    if (s < t[4]) {
        t[4] = s; ti[4] = idx;
        if (s < t[3]) {
            t[4] = t[3]; ti[4] = ti[3]; t[3] = s; ti[3] = idx;
            if (s < t[2]) {
                t[3] = t[2]; ti[3] = ti[2]; t[2] = s; ti[2] = idx;
                if (s < t[1]) {
                    t[2] = t[1]; ti[2] = ti[1]; t[1] = s; ti[1] = idx;
                    if (s < t[0]) { t[1] = t[0]; ti[1] = ti[0]; t[0] = s; ti[0] = idx; }
                }
            }
        }
    }
}

static __device__ __forceinline__ uint32_t quant4(float a, float b, float c, float d) {
    int i0 = __float2int_rn(fminf(fmaxf(a * SCALE, -127.0f), 127.0f));
    int i1 = __float2int_rn(fminf(fmaxf(b * SCALE, -127.0f), 127.0f));
    int i2 = __float2int_rn(fminf(fmaxf(c * SCALE, -127.0f), 127.0f));
    int i3 = __float2int_rn(fminf(fmaxf(d * SCALE, -127.0f), 127.0f));
    return (uint32_t)(i0 & 255) | ((uint32_t)(i1 & 255) << 8) |
           ((uint32_t)(i2 & 255) << 16) | ((uint32_t)(i3 & 255) << 24);
}

// ---------------------------------------------------------------------------
// Prep: int8 quantization + row norms (one warp per row)
// ---------------------------------------------------------------------------
__global__ void prep_bank(const float* __restrict__ bank, int M, int Mpad) {
    int row  = blockIdx.x * 8 + (threadIdx.x >> 5);
    int lane = threadIdx.x & 31;
    if (row >= Mpad) return;
    if (row < M) {
        float4 v = ((const float4*)bank)[(size_t)row * 32 + lane];
        float s = v.x * v.x + v.y * v.y + v.z * v.z + v.w * v.w;
        #pragma unroll
        for (int o = 16; o; o >>= 1) s += __shfl_xor_sync(0xFFFFFFFFu, s, o);
        ((uint32_t*)g_bank_i8)[(size_t)row * 32 + lane] = quant4(v.x, v.y, v.z, v.w);
        if (lane == 0) g_y2[row] = s;
    } else {
        ((uint32_t*)g_bank_i8)[(size_t)row * 32 + lane] = 0u;
        if (lane == 0) g_y2[row] = __int_as_float(0x7F800000);  // +inf
    }
}

// ---------------------------------------------------------------------------
// Main kernel
// ---------------------------------------------------------------------------
static __device__ __forceinline__ void load_b_tile(uint32_t smem_buf,
                                                   int gtile, int tid) {
    const char* gbase = (const char*)g_bank_i8 + (size_t)gtile * CB * D_DIM;
    #pragma unroll
    for (int i = 0; i < 4; i++) {
        int k = tid + i * 256;           // 0..1023 (16B chunks of 128x128B)
        int row = k >> 3;
        int q   = k & 7;
        cp_async16(smem_buf + row * ASTRIDE + q * 16, gbase + row * 128 + q * 16);
    }
    if (tid < 32)
        cp_async16(smem_buf + CB * ASTRIDE + tid * 16,
                   (const char*)g_y2 + (size_t)gtile * CB * 4 + tid * 16);
}

__global__ void __launch_bounds__(256, 1)
knn_main(const float* __restrict__ features, int TILES) {
    extern __shared__ char smem[];
    const uint32_t smem_u = smem_u32(smem);
    const int tid    = threadIdx.x;
    const int wid    = tid >> 5;
    const int lane   = tid & 31;
    const int g      = lane >> 2;       // group id (rows / B cols)
    const int tg     = lane & 3;        // thread-in-group (k / C cols)
    const int warp_m = wid & 3;         // 0..3 -> query rows 32*warp_m
    const int warp_n = wid >> 2;        // 0..1 -> cand cols 64*warp_n
    const int qbase  = blockIdx.x * QB;
    const int split  = blockIdx.y;

    const int T = (TILES - split + NSPLIT - 1) / NSPLIT;

    // Prologue: kick off B tile copies first (overlap with A conversion)
    load_b_tile(smem_u + BBUF(0), split, tid);
    cp_commit();
    if (T > 1) {
        load_b_tile(smem_u + BBUF(1), split + NSPLIT, tid);
        cp_commit();
    }

    // Load + quantize A tile (128 rows x 128 f32 -> int8, padded rows)
    {
        int r = tid >> 1;
        int ch = (tid & 1) * 64;        // column half (elements == bytes)
        const float4* src = (const float4*)(features + (size_t)(qbase + r) * D_DIM + ch);
        char* dst = smem + SMEM_A + r * ASTRIDE + ch;
        #pragma unroll
        for (int u = 0; u < 4; u++) {
            float4 v0 = src[u * 4 + 0];
            float4 v1 = src[u * 4 + 1];
            float4 v2 = src[u * 4 + 2];
            float4 v3 = src[u * 4 + 3];
            uint4 val;
            val.x = quant4(v0.x, v0.y, v0.z, v0.w);
            val.y = quant4(v1.x, v1.y, v1.z, v1.w);
            val.z = quant4(v2.x, v2.y, v2.z, v2.w);
            val.w = quant4(v3.x, v3.y, v3.z, v3.w);
            *(uint4*)(dst + u * 16) = val;
        }
    }
    __syncthreads();

    // Extract A fragments into registers (held for whole kernel)
    uint32_t afr[4][2][4];
    {
        const char* sa = smem + SMEM_A;
        #pragma unroll
        for (int ks = 0; ks < 4; ks++) {
            #pragma unroll
            for (int mt = 0; mt < 2; mt++) {
                int r0 = warp_m * 32 + mt * 16 + g;
                const char* p = sa + r0 * ASTRIDE + ks * 32 + tg * 4;
                afr[ks][mt][0] = *(const uint32_t*)(p);
                afr[ks][mt][1] = *(const uint32_t*)(p + 8 * ASTRIDE);
                afr[ks][mt][2] = *(const uint32_t*)(p + 16);
                afr[ks][mt][3] = *(const uint32_t*)(p + 8 * ASTRIDE + 16);
            }
        }
    }

    const float INF = __int_as_float(0x7F800000);
    float t5[4][5];
    int   t5i[4][5];
    #pragma unroll
    for (int i = 0; i < 4; i++)
        #pragma unroll
        for (int j = 0; j < 5; j++) { t5[i][j] = INF; t5i[i][j] = 0; }

    int cur = 0;
    for (int t = 0; t < T; t++) {
        if (t + 1 < T) cp_wait<1>(); else cp_wait<0>();
        __syncthreads();

        if (t + 2 < T) {
            int pf = cur + 2; if (pf >= 3) pf -= 3;
            load_b_tile(smem_u + BBUF(pf), split + (t + 2) * NSPLIT, tid);
            cp_commit();
        }

        const char*  smB = smem + BBUF(cur);
        const float* smY = (const float*)(smem + BBUF(cur) + CB * ASTRIDE);
        const int gtile = split + t * NSPLIT;

        // Two ns-groups of 4 cols each: halves accumulator register pressure
        #pragma unroll
        for (int ng = 0; ng < 2; ng++) {
            int acc[2][4][4];
            #pragma unroll
            for (int mt = 0; mt < 2; mt++)
                #pragma unroll
                for (int n4 = 0; n4 < 4; n4++)
                    #pragma unroll
                    for (int i = 0; i < 4; i++) acc[mt][n4][i] = 0;

            #pragma unroll
            for (int ks = 0; ks < 4; ks++) {
                uint32_t b0[4], b1[4];
                #pragma unroll
                for (int n4 = 0; n4 < 4; n4++) {
                    int col = warp_n * 64 + (ng * 4 + n4) * 8 + g;
                    const char* p = smB + col * ASTRIDE + ks * 32 + tg * 4;
                    b0[n4] = *(const uint32_t*)(p);
                    b1[n4] = *(const uint32_t*)(p + 16);
                }
                #pragma unroll
                for (int mt = 0; mt < 2; mt++)
                    #pragma unroll
                    for (int n4 = 0; n4 < 4; n4++)
                        imma_16832(acc[mt][n4], afr[ks][mt][0], afr[ks][mt][1],
                                   afr[ks][mt][2], afr[ks][mt][3], b0[n4], b1[n4]);
            }

            // Epilogue: top-5 on s = y2 - 2*dot/scale^2, tracking indices
            #pragma unroll
            for (int n4 = 0; n4 < 4; n4++) {
                int cb = warp_n * 64 + (ng * 4 + n4) * 8 + tg * 2;
                int gidx = gtile * CB + cb;
                float2 yv = *(const float2*)(smY + cb);
                #pragma unroll
                for (int mt = 0; mt < 2; mt++) {
                    float s0 = fmaf((float)acc[mt][n4][0], NEG2IS2, yv.x);
                    float s1 = fmaf((float)acc[mt][n4][1], NEG2IS2, yv.y);
                    float s2 = fmaf((float)acc[mt][n4][2], NEG2IS2, yv.x);
                    float s3 = fmaf((float)acc[mt][n4][3], NEG2IS2, yv.y);
                    top5_update_i(t5[mt * 2 + 0], t5i[mt * 2 + 0], s0, gidx);
                    top5_update_i(t5[mt * 2 + 0], t5i[mt * 2 + 0], s1, gidx + 1);
                    top5_update_i(t5[mt * 2 + 1], t5i[mt * 2 + 1], s2, gidx);
                    top5_update_i(t5[mt * 2 + 1], t5i[mt * 2 + 1], s3, gidx + 1);
                }
            }
        }

        cur++; if (cur >= 3) cur -= 3;
    }

    // Butterfly-merge the 4 tg lanes' lists (same query rows): 20 values -> top5
    #pragma unroll
    for (int li = 0; li < 4; li++) {
        #pragma unroll
        for (int st = 1; st <= 2; st <<= 1) {
            float o0 = __shfl_xor_sync(0xFFFFFFFFu, t5[li][0], st);
            float o1 = __shfl_xor_sync(0xFFFFFFFFu, t5[li][1], st);
            float o2 = __shfl_xor_sync(0xFFFFFFFFu, t5[li][2], st);
            float o3 = __shfl_xor_sync(0xFFFFFFFFu, t5[li][3], st);
            float o4 = __shfl_xor_sync(0xFFFFFFFFu, t5[li][4], st);
            int   i0 = __shfl_xor_sync(0xFFFFFFFFu, t5i[li][0], st);
            int   i1 = __shfl_xor_sync(0xFFFFFFFFu, t5i[li][1], st);
            int   i2 = __shfl_xor_sync(0xFFFFFFFFu, t5i[li][2], st);
            int   i3 = __shfl_xor_sync(0xFFFFFFFFu, t5i[li][3], st);
            int   i4 = __shfl_xor_sync(0xFFFFFFFFu, t5i[li][4], st);
            top5_update_i(t5[li], t5i[li], o0, i0);
            top5_update_i(t5[li], t5i[li], o1, i1);
            top5_update_i(t5[li], t5i[li], o2, i2);
            top5_update_i(t5[li], t5i[li], o3, i3);
            top5_update_i(t5[li], t5i[li], o4, i4);
        }
    }

    // tg==0 lanes write merged candidate indices: comp = split*2 + warp_n
    if (tg == 0) {
        const int comp = split * 2 + warp_n;
        #pragma unroll
        for (int li = 0; li < 4; li++) {
            int row = warp_m * 32 + (li >> 1) * 16 + (li & 1) * 8 + g;
            int* dst = &g_pidx[(size_t)(qbase + row) * PSTRIDE + comp * KNN];
            #pragma unroll
            for (int i = 0; i < KNN; i++) dst[i] = t5i[li][i];
        }
    }
}

// ---------------------------------------------------------------------------
// Merge: warp per query. Recompute exact fp32 d2 for all 90 candidates
// (3 per lane), then 5 rounds of shfl-min selection. Output fp32-exact.
// ---------------------------------------------------------------------------
static __device__ __forceinline__ float exact_d2(const float4* __restrict__ fq,
                                                 const float* __restrict__ bank,
                                                 int idx) {
    const float4* br = (const float4*)(bank + (size_t)idx * D_DIM);
    float s0 = 0.0f, s1 = 0.0f, s2 = 0.0f, s3 = 0.0f;
    #pragma unroll 8
    for (int j = 0; j < 32; j++) {
        float4 a = fq[j];
        float4 b = br[j];
        float d0 = a.x - b.x, d1 = a.y - b.y, d2 = a.z - b.z, d3 = a.w - b.w;
        s0 = fmaf(d0, d0, s0);
        s1 = fmaf(d1, d1, s1);
        s2 = fmaf(d2, d2, s2);
        s3 = fmaf(d3, d3, s3);
    }
    return (s0 + s1) + (s2 + s3);
}

__global__ void knn_merge(float* __restrict__ out,
                          const float* __restrict__ features,
                          const float* __restrict__ bank,
                          const float* __restrict__ minv,
                          const float* __restrict__ maxv, int N) {
    const int lane = threadIdx.x & 31;
    const int q = blockIdx.x * 8 + (threadIdx.x >> 5);
    if (q >= N) return;
    const float INF = __int_as_float(0x7F800000);

    const int* pi = g_pidx + (size_t)q * PSTRIDE;
    const float4* fq = (const float4*)(features + (size_t)q * D_DIM);

    float v0 = exact_d2(fq, bank, pi[lane]);
    float v1 = exact_d2(fq, bank, pi[lane + 32]);
    float v2 = (lane + 64 < PSTRIDE) ? exact_d2(fq, bank, pi[lane + 64]) : INF;
    // sort v0 <= v1 <= v2
    { float a = fminf(v0, v1), b = fmaxf(v0, v1); v0 = a; v1 = b; }
    { float a = fminf(v1, v2), b = fmaxf(v1, v2); v1 = a; v2 = b; }
    { float a = fminf(v0, v1), b = fmaxf(v0, v1); v0 = a; v1 = b; }

    const float mn  = *minv;
    const float inv = 1.0f / (*maxv - mn);

    int idx = 0;
    float sum = 0.0f;
    #pragma unroll
    for (int k = 0; k < KNN; k++) {
        float h = (idx == 0) ? v0 : (idx == 1) ? v1 : (idx == 2) ? v2 : INF;
        float m = h;
        #pragma unroll
        for (int o = 16; o; o >>= 1) m = fminf(m, __shfl_xor_sync(0xFFFFFFFFu, m, o));
        unsigned ball = __ballot_sync(0xFFFFFFFFu, h == m);
        int src = __ffs(ball) - 1;
        if (lane == src) idx++;
        float d = sqrtf(fmaxf(m, 0.0f));
        sum += (d - mn) * inv;
    }
    if (lane == 0) out[q] = sum * (1.0f / KNN);
}

// ---------------------------------------------------------------------------
// Launch
// ---------------------------------------------------------------------------
extern "C" void kernel_launch(void* const* d_in, const int* in_sizes, int n_in,
                              void* d_out, int out_size) {
    const float* features = (const float*)d_in[0];
    const float* bank     = (const float*)d_in[1];
    const float* minv     = (const float*)d_in[2];
    const float* maxv     = (const float*)d_in[3];
    (void)n_in;

    const int N = in_sizes[0] / D_DIM;         // 2048
    const int M = in_sizes[1] / D_DIM;         // 100000
    const int TILES = (M + CB - 1) / CB;       // 782
    const int Mpad = TILES * CB;

    cudaFuncSetAttribute(knn_main, cudaFuncAttributeMaxDynamicSharedMemorySize,
                         SMEM_TOTAL);

    prep_bank<<<(Mpad + 7) / 8, 256>>>(bank, M, Mpad);
    knn_main<<<dim3(N / QB, NSPLIT), 256, SMEM_TOTAL>>>(features, TILES);
    knn_merge<<<(N + 7) / 8, 256>>>((float*)d_out, features, bank, minv, maxv, N);
    (void)out_size;
}

// round 13
// speedup vs baseline: 1.3200x; 1.3200x over previous
#include <cuda_runtime.h>
#include <cuda_fp16.h>
#include <cstdint>
#include <cstddef>

// ---------------------------------------------------------------------------
// GroupedKNNEstimator: out[q] = mean_k ( (sqrt(knn_d2_k) - min) / (max - min) )
// N=2048 queries, M=100000 bank rows, D=128, K=5.
// R9: f16-in/f16-acc mma.m16n8k16 screening (possible 2x rate vs f32-acc on
// the legacy tensor pipe), tracking candidate indices; merge recomputes exact
// fp32 d2 for the 90 survivors per query. Output fp32-exact.
// ---------------------------------------------------------------------------

#define D_DIM   128
#define QB      128          // queries per CTA (CTA tile M)
#define CB      128          // candidates per tile (CTA tile N)
#define NSPLIT  9            // M-dimension splits (grid.y)
#define KNN     5
#define MAXN    2048
#define MAXROWS 100096       // M padded to CB multiple (782*128)
#define PARTS   (NSPLIT * 2) // partial top-5 lists per query (2 per CTA)
#define PSTRIDE (PARTS * KNN)// 90 candidates per query

#define ASTRIDE 272          // padded row stride (bytes) for 128 f16 = 256B rows

// SMEM layout: A tile + 3 B buffers (B tile + y2 vector each)
#define SMEM_A     0
#define A_BYTES    (QB * ASTRIDE)          // 34816
#define BUF_BYTES  (CB * ASTRIDE + 512)    // 35328 (B + 128 y2 floats)
#define BBUF(i)    (A_BYTES + (i) * BUF_BYTES)
#define SMEM_TOTAL (A_BYTES + 3 * BUF_BYTES)   // 140800

__device__ __half g_bank_h[(size_t)MAXROWS * D_DIM];
__device__ float g_y2[MAXROWS];
__device__ int g_pidx[(size_t)MAXN * PSTRIDE];   // [q][90] candidate indices

static __device__ __forceinline__ uint32_t smem_u32(const void* p) {
    uint32_t a;
    asm("{ .reg .u64 t; cvta.to.shared.u64 t, %1; cvt.u32.u64 %0, t; }"
        : "=r"(a) : "l"(p));
    return a;
}

static __device__ __forceinline__ void cp_async16(uint32_t dst, const void* src) {
    asm volatile("cp.async.cg.shared.global [%0], [%1], 16;" :: "r"(dst), "l"(src));
}
static __device__ __forceinline__ void cp_commit() {
    asm volatile("cp.async.commit_group;" ::: "memory");
}
template <int NN>
static __device__ __forceinline__ void cp_wait() {
    asm volatile("cp.async.wait_group %0;" :: "n"(NN) : "memory");
}

// f16 inputs, f16 accumulators: C (2 regs of f16x2) += A * B
static __device__ __forceinline__ void hmma_16816_f16(uint32_t (&c)[2],
                                                      uint32_t a0, uint32_t a1,
                                                      uint32_t a2, uint32_t a3,
                                                      uint32_t b0, uint32_t b1) {
    asm volatile(
        "mma.sync.aligned.m16n8k16.row.col.f16.f16.f16.f16 "
        "{%0,%1}, {%2,%3,%4,%5}, {%6,%7}, {%0,%1};"
        : "+r"(c[0]), "+r"(c[1])
        : "r"(a0), "r"(a1), "r"(a2), "r"(a3), "r"(b0), "r"(b1));
}

static __device__ __forceinline__ void top5_update_i(float (&t)[5], int (&ti)[5],
                                                     float s, int idx) {
    if (s < t[4]) {
        t[4] = s; ti[4] = idx;
        if (s < t[3]) {
            t[4] = t[3]; ti[4] = ti[3]; t[3] = s; ti[3] = idx;
            if (s < t[2]) {
                t[3] = t[2]; ti[3] = ti[2]; t[2] = s; ti[2] = idx;
                if (s < t[1]) {
                    t[2] = t[1]; ti[2] = ti[1]; t[1] = s; ti[1] = idx;
                    if (s < t[0]) { t[1] = t[0]; ti[1] = ti[0]; t[0] = s; ti[0] = idx; }
                }
            }
        }
    }
}

// ---------------------------------------------------------------------------
// Prep: f16 conversion + row norms (one warp per row)
// ---------------------------------------------------------------------------
__global__ void prep_bank(const float* __restrict__ bank, int M, int Mpad) {
    int row  = blockIdx.x * 8 + (threadIdx.x >> 5);
    int lane = threadIdx.x & 31;
    if (row >= Mpad) return;
    if (row < M) {
        float4 v = ((const float4*)bank)[(size_t)row * 32 + lane];
        float s = v.x * v.x + v.y * v.y + v.z * v.z + v.w * v.w;
        #pragma unroll
        for (int o = 16; o; o >>= 1) s += __shfl_xor_sync(0xFFFFFFFFu, s, o);
        __half2 h0 = __floats2half2_rn(v.x, v.y);
        __half2 h1 = __floats2half2_rn(v.z, v.w);
        uint2 pk;
        pk.x = *reinterpret_cast<uint32_t*>(&h0);
        pk.y = *reinterpret_cast<uint32_t*>(&h1);
        ((uint2*)g_bank_h)[(size_t)row * 32 + lane] = pk;
        if (lane == 0) g_y2[row] = s;
    } else {
        ((uint2*)g_bank_h)[(size_t)row * 32 + lane] = make_uint2(0u, 0u);
        if (lane == 0) g_y2[row] = __int_as_float(0x7F800000);  // +inf
    }
}

// ---------------------------------------------------------------------------
// Main kernel
// ---------------------------------------------------------------------------
static __device__ __forceinline__ void load_b_tile(uint32_t smem_buf,
                                                   int gtile, int tid) {
    const char* gbase = (const char*)g_bank_h + (size_t)gtile * CB * 256;
    #pragma unroll
    for (int i = 0; i < 8; i++) {
        int k = tid + i * 256;           // 0..2047 (16B chunks of 128x256B)
        int row = k >> 4;
        int q   = k & 15;
        cp_async16(smem_buf + row * ASTRIDE + q * 16, gbase + row * 256 + q * 16);
    }
    if (tid < 32)
        cp_async16(smem_buf + CB * ASTRIDE + tid * 16,
                   (const char*)g_y2 + (size_t)gtile * CB * 4 + tid * 16);
}

__global__ void __launch_bounds__(256, 1)
knn_main(const float* __restrict__ features, int TILES) {
    extern __shared__ char smem[];
    const uint32_t smem_u = smem_u32(smem);
    const int tid    = threadIdx.x;
    const int wid    = tid >> 5;
    const int lane   = tid & 31;
    const int g      = lane >> 2;       // group id (rows / B cols)
    const int tg     = lane & 3;        // thread-in-group (k / C cols)
    const int warp_m = wid & 3;         // 0..3 -> query rows 32*warp_m
    const int warp_n = wid >> 2;        // 0..1 -> cand cols 64*warp_n
    const int qbase  = blockIdx.x * QB;
    const int split  = blockIdx.y;

    const int T = (TILES - split + NSPLIT - 1) / NSPLIT;

    // Prologue: kick off B tile copies first (overlap with A conversion)
    load_b_tile(smem_u + BBUF(0), split, tid);
    cp_commit();
    if (T > 1) {
        load_b_tile(smem_u + BBUF(1), split + NSPLIT, tid);
        cp_commit();
    }

    // Load + convert A tile (128 rows x 128 f32 -> f16, padded rows)
    {
        int r = tid >> 1;
        int ch = (tid & 1) * 64;        // column half
        const float4* src = (const float4*)(features + (size_t)(qbase + r) * D_DIM + ch);
        char* dst = smem + SMEM_A + r * ASTRIDE + ch * 2;
        #pragma unroll
        for (int u = 0; u < 8; u++) {
            float4 v0 = src[u * 2];
            float4 v1 = src[u * 2 + 1];
            __half2 b0 = __floats2half2_rn(v0.x, v0.y);
            __half2 b1 = __floats2half2_rn(v0.z, v0.w);
            __half2 b2 = __floats2half2_rn(v1.x, v1.y);
            __half2 b3 = __floats2half2_rn(v1.z, v1.w);
            uint4 val;
            val.x = *reinterpret_cast<uint32_t*>(&b0);
            val.y = *reinterpret_cast<uint32_t*>(&b1);
            val.z = *reinterpret_cast<uint32_t*>(&b2);
            val.w = *reinterpret_cast<uint32_t*>(&b3);
            *(uint4*)(dst + u * 16) = val;
        }
    }
    __syncthreads();

    // Extract A fragments into registers (held for whole kernel)
    uint32_t afr[8][2][4];
    {
        const char* sa = smem + SMEM_A;
        #pragma unroll
        for (int ks = 0; ks < 8; ks++) {
            #pragma unroll
            for (int mt = 0; mt < 2; mt++) {
                int r0 = warp_m * 32 + mt * 16 + g;
                const char* p = sa + r0 * ASTRIDE + (ks * 16 + tg * 2) * 2;
                afr[ks][mt][0] = *(const uint32_t*)(p);
                afr[ks][mt][1] = *(const uint32_t*)(p + 8 * ASTRIDE);
                afr[ks][mt][2] = *(const uint32_t*)(p + 16);
                afr[ks][mt][3] = *(const uint32_t*)(p + 8 * ASTRIDE + 16);
            }
        }
    }

    const float INF = __int_as_float(0x7F800000);
    float t5[4][5];
    int   t5i[4][5];
    #pragma unroll
    for (int i = 0; i < 4; i++)
        #pragma unroll
        for (int j = 0; j < 5; j++) { t5[i][j] = INF; t5i[i][j] = 0; }

    int cur = 0;
    for (int t = 0; t < T; t++) {
        if (t + 1 < T) cp_wait<1>(); else cp_wait<0>();
        __syncthreads();

        if (t + 2 < T) {
            int pf = cur + 2; if (pf >= 3) pf -= 3;
            load_b_tile(smem_u + BBUF(pf), split + (t + 2) * NSPLIT, tid);
            cp_commit();
        }

        const char*  smB = smem + BBUF(cur);
        const float* smY = (const float*)(smem + BBUF(cur) + CB * ASTRIDE);
        const int gtile = split + t * NSPLIT;

        // Two ns-groups of 4 cols each (keeps accumulator pressure low)
        #pragma unroll
        for (int ng = 0; ng < 2; ng++) {
            uint32_t acc[2][4][2];
            #pragma unroll
            for (int mt = 0; mt < 2; mt++)
                #pragma unroll
                for (int n4 = 0; n4 < 4; n4++) {
                    acc[mt][n4][0] = 0u; acc[mt][n4][1] = 0u;
                }

            #pragma unroll
            for (int ks = 0; ks < 8; ks++) {
                uint32_t b0[4], b1[4];
                #pragma unroll
                for (int n4 = 0; n4 < 4; n4++) {
                    int col = warp_n * 64 + (ng * 4 + n4) * 8 + g;
                    const char* p = smB + col * ASTRIDE + (ks * 16 + tg * 2) * 2;
                    b0[n4] = *(const uint32_t*)(p);
                    b1[n4] = *(const uint32_t*)(p + 16);
                }
                #pragma unroll
                for (int mt = 0; mt < 2; mt++)
                    #pragma unroll
                    for (int n4 = 0; n4 < 4; n4++)
                        hmma_16816_f16(acc[mt][n4], afr[ks][mt][0], afr[ks][mt][1],
                                       afr[ks][mt][2], afr[ks][mt][3],
                                       b0[n4], b1[n4]);
            }

            // Epilogue: top-5 on s = y2 - 2*dot, tracking indices.
            // acc[..][0] = {col tg*2, col tg*2+1} row g; acc[..][1] = row g+8.
            #pragma unroll
            for (int n4 = 0; n4 < 4; n4++) {
                int cb = warp_n * 64 + (ng * 4 + n4) * 8 + tg * 2;
                int gidx = gtile * CB + cb;
                float2 yv = *(const float2*)(smY + cb);
                #pragma unroll
                for (int mt = 0; mt < 2; mt++) {
                    float2 p0 = __half22float2(*reinterpret_cast<__half2*>(&acc[mt][n4][0]));
                    float2 p1 = __half22float2(*reinterpret_cast<__half2*>(&acc[mt][n4][1]));
                    float s0 = fmaf(-2.0f, p0.x, yv.x);
                    float s1 = fmaf(-2.0f, p0.y, yv.y);
                    float s2 = fmaf(-2.0f, p1.x, yv.x);
                    float s3 = fmaf(-2.0f, p1.y, yv.y);
                    top5_update_i(t5[mt * 2 + 0], t5i[mt * 2 + 0], s0, gidx);
                    top5_update_i(t5[mt * 2 + 0], t5i[mt * 2 + 0], s1, gidx + 1);
                    top5_update_i(t5[mt * 2 + 1], t5i[mt * 2 + 1], s2, gidx);
                    top5_update_i(t5[mt * 2 + 1], t5i[mt * 2 + 1], s3, gidx + 1);
                }
            }
        }

        cur++; if (cur >= 3) cur -= 3;
    }

    // Butterfly-merge the 4 tg lanes' lists (same query rows): 20 values -> top5
    #pragma unroll
    for (int li = 0; li < 4; li++) {
        #pragma unroll
        for (int st = 1; st <= 2; st <<= 1) {
            float o0 = __shfl_xor_sync(0xFFFFFFFFu, t5[li][0], st);
            float o1 = __shfl_xor_sync(0xFFFFFFFFu, t5[li][1], st);
            float o2 = __shfl_xor_sync(0xFFFFFFFFu, t5[li][2], st);
            float o3 = __shfl_xor_sync(0xFFFFFFFFu, t5[li][3], st);
            float o4 = __shfl_xor_sync(0xFFFFFFFFu, t5[li][4], st);
            int   i0 = __shfl_xor_sync(0xFFFFFFFFu, t5i[li][0], st);
            int   i1 = __shfl_xor_sync(0xFFFFFFFFu, t5i[li][1], st);
            int   i2 = __shfl_xor_sync(0xFFFFFFFFu, t5i[li][2], st);
            int   i3 = __shfl_xor_sync(0xFFFFFFFFu, t5i[li][3], st);
            int   i4 = __shfl_xor_sync(0xFFFFFFFFu, t5i[li][4], st);
            top5_update_i(t5[li], t5i[li], o0, i0);
            top5_update_i(t5[li], t5i[li], o1, i1);
            top5_update_i(t5[li], t5i[li], o2, i2);
            top5_update_i(t5[li], t5i[li], o3, i3);
            top5_update_i(t5[li], t5i[li], o4, i4);
        }
    }

    // tg==0 lanes write merged candidate indices: comp = split*2 + warp_n
    if (tg == 0) {
        const int comp = split * 2 + warp_n;
        #pragma unroll
        for (int li = 0; li < 4; li++) {
            int row = warp_m * 32 + (li >> 1) * 16 + (li & 1) * 8 + g;
            int* dst = &g_pidx[(size_t)(qbase + row) * PSTRIDE + comp * KNN];
            #pragma unroll
            for (int i = 0; i < KNN; i++) dst[i] = t5i[li][i];
        }
    }
}

// ---------------------------------------------------------------------------
// Merge: warp per query. Recompute exact fp32 d2 for all 90 candidates
// (3 per lane), then 5 rounds of shfl-min selection. Output fp32-exact.
// ---------------------------------------------------------------------------
static __device__ __forceinline__ float exact_d2(const float4* __restrict__ fq,
                                                 const float* __restrict__ bank,
                                                 int idx) {
    const float4* br = (const float4*)(bank + (size_t)idx * D_DIM);
    float s0 = 0.0f, s1 = 0.0f, s2 = 0.0f, s3 = 0.0f;
    #pragma unroll 8
    for (int j = 0; j < 32; j++) {
        float4 a = fq[j];
        float4 b = br[j];
        float d0 = a.x - b.x, d1 = a.y - b.y, d2 = a.z - b.z, d3 = a.w - b.w;
        s0 = fmaf(d0, d0, s0);
        s1 = fmaf(d1, d1, s1);
        s2 = fmaf(d2, d2, s2);
        s3 = fmaf(d3, d3, s3);
    }
    return (s0 + s1) + (s2 + s3);
}

__global__ void knn_merge(float* __restrict__ out,
                          const float* __restrict__ features,
                          const float* __restrict__ bank,
                          const float* __restrict__ minv,
                          const float* __restrict__ maxv, int N) {
    const int lane = threadIdx.x & 31;
    const int q = blockIdx.x * 8 + (threadIdx.x >> 5);
    if (q >= N) return;
    const float INF = __int_as_float(0x7F800000);

    const int* pi = g_pidx + (size_t)q * PSTRIDE;
    const float4* fq = (const float4*)(features + (size_t)q * D_DIM);

    float v0 = exact_d2(fq, bank, pi[lane]);
    float v1 = exact_d2(fq, bank, pi[lane + 32]);
    float v2 = (lane + 64 < PSTRIDE) ? exact_d2(fq, bank, pi[lane + 64]) : INF;
    // sort v0 <= v1 <= v2
    { float a = fminf(v0, v1), b = fmaxf(v0, v1); v0 = a; v1 = b; }
    { float a = fminf(v1, v2), b = fmaxf(v1, v2); v1 = a; v2 = b; }
    { float a = fminf(v0, v1), b = fmaxf(v0, v1); v0 = a; v1 = b; }

    const float mn  = *minv;
    const float inv = 1.0f / (*maxv - mn);

    int idx = 0;
    float sum = 0.0f;
    #pragma unroll
    for (int k = 0; k < KNN; k++) {
        float h = (idx == 0) ? v0 : (idx == 1) ? v1 : (idx == 2) ? v2 : INF;
        float m = h;
        #pragma unroll
        for (int o = 16; o; o >>= 1) m = fminf(m, __shfl_xor_sync(0xFFFFFFFFu, m, o));
        unsigned ball = __ballot_sync(0xFFFFFFFFu, h == m);
        int src = __ffs(ball) - 1;
        if (lane == src) idx++;
        float d = sqrtf(fmaxf(m, 0.0f));
        sum += (d - mn) * inv;
    }
    if (lane == 0) out[q] = sum * (1.0f / KNN);
}

// ---------------------------------------------------------------------------
// Launch
// ---------------------------------------------------------------------------
extern "C" void kernel_launch(void* const* d_in, const int* in_sizes, int n_in,
                              void* d_out, int out_size) {
    const float* features = (const float*)d_in[0];
    const float* bank     = (const float*)d_in[1];
    const float* minv     = (const float*)d_in[2];
    const float* maxv     = (const float*)d_in[3];
    (void)n_in;

    const int N = in_sizes[0] / D_DIM;         // 2048
    const int M = in_sizes[1] / D_DIM;         // 100000
    const int TILES = (M + CB - 1) / CB;       // 782
    const int Mpad = TILES * CB;

    cudaFuncSetAttribute(knn_main, cudaFuncAttributeMaxDynamicSharedMemorySize,
                         SMEM_TOTAL);

    prep_bank<<<(Mpad + 7) / 8, 256>>>(bank, M, Mpad);
    knn_main<<<dim3(N / QB, NSPLIT), 256, SMEM_TOTAL>>>(features, TILES);
    knn_merge<<<(N + 7) / 8, 256>>>((float*)d_out, features, bank, minv, maxv, N);
    (void)out_size;
}

// round 15
// speedup vs baseline: 2.3607x; 1.7884x over previous
#include <cuda_runtime.h>
#include <cuda_bf16.h>
#include <cstdint>
#include <cstddef>

// ---------------------------------------------------------------------------
// GroupedKNNEstimator: out[q] = mean_k ( (sqrt(knn_d2_k) - min) / (max - min) )
// N=2048 queries, M=100000 bank rows, D=128, K=5.
// R14: bf16/f32-acc m16n8k16 (proven fastest legacy-MMA op), 512 threads
// (4 warps/SMSP, 4x4 warp grid, 32x32 warp tile) for tensor-pipe latency
// hiding, early-out epilogue, value-based top-5 partials.
// ---------------------------------------------------------------------------

#define D_DIM   128
#define QB      128          // queries per CTA (CTA tile M)
#define CB      128          // candidates per tile (CTA tile N)
#define NSPLIT  9            // M-dimension splits (grid.y)
#define KNN     5
#define MAXN    2048
#define MAXROWS 100096       // M padded to CB multiple (782*128)
#define PARTS   (NSPLIT * 4) // partial top-5 lists per query (4 per CTA)
#define PSTRIDE (PARTS * KNN)// 180 floats per query

#define ASTRIDE 272          // padded row stride (bytes) for 128 bf16 = 256B rows

// SMEM layout: A tile + 3 B buffers (B tile + y2 vector each)
#define SMEM_A     0
#define A_BYTES    (QB * ASTRIDE)          // 34816
#define BUF_BYTES  (CB * ASTRIDE + 512)    // 35328 (B + 128 y2 floats)
#define BBUF(i)    (A_BYTES + (i) * BUF_BYTES)
#define SMEM_TOTAL (A_BYTES + 3 * BUF_BYTES)   // 140800

__device__ __nv_bfloat16 g_bank_bf16[(size_t)MAXROWS * D_DIM];
__device__ float g_y2[MAXROWS];
__device__ float g_x2[MAXN];
__device__ float g_partial[(size_t)MAXN * PSTRIDE];   // [q][180]

static __device__ __forceinline__ uint32_t smem_u32(const void* p) {
    uint32_t a;
    asm("{ .reg .u64 t; cvta.to.shared.u64 t, %1; cvt.u32.u64 %0, t; }"
        : "=r"(a) : "l"(p));
    return a;
}

static __device__ __forceinline__ void cp_async16(uint32_t dst, const void* src) {
    asm volatile("cp.async.cg.shared.global [%0], [%1], 16;" :: "r"(dst), "l"(src));
}
static __device__ __forceinline__ void cp_commit() {
    asm volatile("cp.async.commit_group;" ::: "memory");
}
template <int NN>
static __device__ __forceinline__ void cp_wait() {
    asm volatile("cp.async.wait_group %0;" :: "n"(NN) : "memory");
}

static __device__ __forceinline__ void mma_16816(float (&c)[4],
                                                 uint32_t a0, uint32_t a1,
                                                 uint32_t a2, uint32_t a3,
                                                 uint32_t b0, uint32_t b1) {
    asm volatile(
        "mma.sync.aligned.m16n8k16.row.col.f32.bf16.bf16.f32 "
        "{%0,%1,%2,%3}, {%4,%5,%6,%7}, {%8,%9}, {%0,%1,%2,%3};"
        : "+f"(c[0]), "+f"(c[1]), "+f"(c[2]), "+f"(c[3])
        : "r"(a0), "r"(a1), "r"(a2), "r"(a3), "r"(b0), "r"(b1));
}

static __device__ __forceinline__ void top5_update(float (&t)[5], float s) {
    if (s < t[4]) {
        t[4] = s;
        if (s < t[3]) {
            t[4] = t[3]; t[3] = s;
            if (s < t[2]) {
                t[3] = t[2]; t[2] = s;
                if (s < t[1]) {
                    t[2] = t[1]; t[1] = s;
                    if (s < t[0]) { t[1] = t[0]; t[0] = s; }
                }
            }
        }
    }
}

// ---------------------------------------------------------------------------
// Prep kernels: bf16 conversion + row norms (one warp per row)
// ---------------------------------------------------------------------------
__global__ void prep_bank(const float* __restrict__ bank, int M, int Mpad) {
    int row  = blockIdx.x * 8 + (threadIdx.x >> 5);
    int lane = threadIdx.x & 31;
    if (row >= Mpad) return;
    if (row < M) {
        float4 v = ((const float4*)bank)[(size_t)row * 32 + lane];
        float s = v.x * v.x + v.y * v.y + v.z * v.z + v.w * v.w;
        #pragma unroll
        for (int o = 16; o; o >>= 1) s += __shfl_xor_sync(0xFFFFFFFFu, s, o);
        __nv_bfloat162 h0 = __floats2bfloat162_rn(v.x, v.y);
        __nv_bfloat162 h1 = __floats2bfloat162_rn(v.z, v.w);
        uint2 pk;
        pk.x = *reinterpret_cast<uint32_t*>(&h0);
        pk.y = *reinterpret_cast<uint32_t*>(&h1);
        ((uint2*)g_bank_bf16)[(size_t)row * 32 + lane] = pk;
        if (lane == 0) g_y2[row] = s;
    } else {
        ((uint2*)g_bank_bf16)[(size_t)row * 32 + lane] = make_uint2(0u, 0u);
        if (lane == 0) g_y2[row] = __int_as_float(0x7F800000);  // +inf
    }
}

__global__ void prep_feat(const float* __restrict__ f, int N) {
    int row  = blockIdx.x * 8 + (threadIdx.x >> 5);
    int lane = threadIdx.x & 31;
    if (row >= N) return;
    float4 v = ((const float4*)f)[(size_t)row * 32 + lane];
    float s = v.x * v.x + v.y * v.y + v.z * v.z + v.w * v.w;
    #pragma unroll
    for (int o = 16; o; o >>= 1) s += __shfl_xor_sync(0xFFFFFFFFu, s, o);
    if (lane == 0) g_x2[row] = s;
}

// ---------------------------------------------------------------------------
// Main kernel: 512 threads, 4x4 warp grid, 32x32 warp tile
// ---------------------------------------------------------------------------
static __device__ __forceinline__ void load_b_tile(uint32_t smem_buf,
                                                   int gtile, int tid) {
    const char* gbase = (const char*)g_bank_bf16 + (size_t)gtile * CB * 256;
    #pragma unroll
    for (int i = 0; i < 4; i++) {
        int k = tid + i * 512;           // 0..2047 (16B chunks of 128x256B)
        int row = k >> 4;
        int q   = k & 15;
        cp_async16(smem_buf + row * ASTRIDE + q * 16, gbase + row * 256 + q * 16);
    }
    if (tid < 32)
        cp_async16(smem_buf + CB * ASTRIDE + tid * 16,
                   (const char*)g_y2 + (size_t)gtile * CB * 4 + tid * 16);
}

__global__ void __launch_bounds__(512, 1)
knn_main(const float* __restrict__ features, int TILES) {
    extern __shared__ char smem[];
    const uint32_t smem_u = smem_u32(smem);
    const int tid    = threadIdx.x;
    const int wid    = tid >> 5;
    const int lane   = tid & 31;
    const int g      = lane >> 2;       // group id (rows / B cols)
    const int tg     = lane & 3;        // thread-in-group (k / C cols)
    const int warp_m = wid & 3;         // 0..3 -> query rows 32*warp_m
    const int warp_n = wid >> 2;        // 0..3 -> cand cols 32*warp_n
    const int qbase  = blockIdx.x * QB;
    const int split  = blockIdx.y;

    const int T = (TILES - split + NSPLIT - 1) / NSPLIT;

    // Prologue: kick off B tile copies first (overlap with A conversion)
    load_b_tile(smem_u + BBUF(0), split, tid);
    cp_commit();
    if (T > 1) {
        load_b_tile(smem_u + BBUF(1), split + NSPLIT, tid);
        cp_commit();
    }

    // Load + convert A tile (128 rows x 128 f32 -> bf16, padded rows)
    {
        int r = tid >> 2;
        int ch = (tid & 3) * 32;        // column quarter
        const float4* src = (const float4*)(features + (size_t)(qbase + r) * D_DIM + ch);
        char* dst = smem + SMEM_A + r * ASTRIDE + ch * 2;
        #pragma unroll
        for (int u = 0; u < 4; u++) {
            float4 v0 = src[u * 2];
            float4 v1 = src[u * 2 + 1];
            __nv_bfloat162 b0 = __floats2bfloat162_rn(v0.x, v0.y);
            __nv_bfloat162 b1 = __floats2bfloat162_rn(v0.z, v0.w);
            __nv_bfloat162 b2 = __floats2bfloat162_rn(v1.x, v1.y);
            __nv_bfloat162 b3 = __floats2bfloat162_rn(v1.z, v1.w);
            uint4 val;
            val.x = *reinterpret_cast<uint32_t*>(&b0);
            val.y = *reinterpret_cast<uint32_t*>(&b1);
            val.z = *reinterpret_cast<uint32_t*>(&b2);
            val.w = *reinterpret_cast<uint32_t*>(&b3);
            *(uint4*)(dst + u * 16) = val;
        }
    }
    __syncthreads();

    // Extract A fragments into registers (held for whole kernel): 64 regs
    uint32_t afr[8][2][4];
    {
        const char* sa = smem + SMEM_A;
        #pragma unroll
        for (int ks = 0; ks < 8; ks++) {
            #pragma unroll
            for (int mt = 0; mt < 2; mt++) {
                int r0 = warp_m * 32 + mt * 16 + g;
                const char* p = sa + r0 * ASTRIDE + (ks * 16 + tg * 2) * 2;
                afr[ks][mt][0] = *(const uint32_t*)(p);
                afr[ks][mt][1] = *(const uint32_t*)(p + 8 * ASTRIDE);
                afr[ks][mt][2] = *(const uint32_t*)(p + 16);
                afr[ks][mt][3] = *(const uint32_t*)(p + 8 * ASTRIDE + 16);
            }
        }
    }

    const float INF = __int_as_float(0x7F800000);
    float t5[4][5];
    #pragma unroll
    for (int i = 0; i < 4; i++)
        #pragma unroll
        for (int j = 0; j < 5; j++) t5[i][j] = INF;

    int cur = 0;
    for (int t = 0; t < T; t++) {
        if (t + 1 < T) cp_wait<1>(); else cp_wait<0>();
        __syncthreads();

        if (t + 2 < T) {
            int pf = cur + 2; if (pf >= 3) pf -= 3;
            load_b_tile(smem_u + BBUF(pf), split + (t + 2) * NSPLIT, tid);
            cp_commit();
        }

        const char*  smB = smem + BBUF(cur);
        const float* smY = (const float*)(smem + BBUF(cur) + CB * ASTRIDE);

        // Two ns-groups of 2 cols-of-8 each (acc = 16 regs per group)
        #pragma unroll
        for (int ng = 0; ng < 2; ng++) {
            float acc[2][2][4];
            #pragma unroll
            for (int mt = 0; mt < 2; mt++)
                #pragma unroll
                for (int n2 = 0; n2 < 2; n2++)
                    #pragma unroll
                    for (int i = 0; i < 4; i++) acc[mt][n2][i] = 0.0f;

            #pragma unroll
            for (int ks = 0; ks < 8; ks++) {
                uint32_t b0[2], b1[2];
                #pragma unroll
                for (int n2 = 0; n2 < 2; n2++) {
                    int col = warp_n * 32 + (ng * 2 + n2) * 8 + g;
                    const char* p = smB + col * ASTRIDE + (ks * 16 + tg * 2) * 2;
                    b0[n2] = *(const uint32_t*)(p);
                    b1[n2] = *(const uint32_t*)(p + 16);
                }
                #pragma unroll
                for (int mt = 0; mt < 2; mt++)
                    #pragma unroll
                    for (int n2 = 0; n2 < 2; n2++)
                        mma_16816(acc[mt][n2], afr[ks][mt][0], afr[ks][mt][1],
                                  afr[ks][mt][2], afr[ks][mt][3], b0[n2], b1[n2]);
            }

            // Early-out epilogue: top-5 on s = y2 - 2*dot
            #pragma unroll
            for (int n2 = 0; n2 < 2; n2++) {
                int cb = warp_n * 32 + (ng * 2 + n2) * 8 + tg * 2;
                float2 yv = *(const float2*)(smY + cb);
                #pragma unroll
                for (int mt = 0; mt < 2; mt++) {
                    float s0 = fmaf(-2.0f, acc[mt][n2][0], yv.x);
                    float s1 = fmaf(-2.0f, acc[mt][n2][1], yv.y);
                    float s2 = fmaf(-2.0f, acc[mt][n2][2], yv.x);
                    float s3 = fmaf(-2.0f, acc[mt][n2][3], yv.y);
                    // rows g (list mt*2) and g+8 (list mt*2+1)
                    if (fminf(s0, s1) < t5[mt * 2 + 0][4]) {
                        top5_update(t5[mt * 2 + 0], s0);
                        top5_update(t5[mt * 2 + 0], s1);
                    }
                    if (fminf(s2, s3) < t5[mt * 2 + 1][4]) {
                        top5_update(t5[mt * 2 + 1], s2);
                        top5_update(t5[mt * 2 + 1], s3);
                    }
                }
            }
        }

        cur++; if (cur >= 3) cur -= 3;
    }

    // Butterfly-merge the 4 tg lanes' lists (same query rows): 20 values -> top5
    #pragma unroll
    for (int li = 0; li < 4; li++) {
        #pragma unroll
        for (int st = 1; st <= 2; st <<= 1) {
            float o0 = __shfl_xor_sync(0xFFFFFFFFu, t5[li][0], st);
            float o1 = __shfl_xor_sync(0xFFFFFFFFu, t5[li][1], st);
            float o2 = __shfl_xor_sync(0xFFFFFFFFu, t5[li][2], st);
            float o3 = __shfl_xor_sync(0xFFFFFFFFu, t5[li][3], st);
            float o4 = __shfl_xor_sync(0xFFFFFFFFu, t5[li][4], st);
            top5_update(t5[li], o0);
            top5_update(t5[li], o1);
            top5_update(t5[li], o2);
            top5_update(t5[li], o3);
            top5_update(t5[li], o4);
        }
    }

    // tg==0 lanes write merged top-5: comp = split*4 + warp_n, layout [q][180]
    if (tg == 0) {
        const int comp = split * 4 + warp_n;
        #pragma unroll
        for (int li = 0; li < 4; li++) {
            int row = warp_m * 32 + (li >> 1) * 16 + (li & 1) * 8 + g;
            float* dst = &g_partial[(size_t)(qbase + row) * PSTRIDE + comp * KNN];
            #pragma unroll
            for (int i = 0; i < KNN; i++) dst[i] = t5[li][i];
        }
    }
}

// ---------------------------------------------------------------------------
// Merge: warp per query. Lanes scan 180 values, 5 rounds of shfl-min selection.
// ---------------------------------------------------------------------------
__global__ void knn_merge(float* __restrict__ out,
                          const float* __restrict__ minv,
                          const float* __restrict__ maxv, int N) {
    const int lane = threadIdx.x & 31;
    const int q = blockIdx.x * 8 + (threadIdx.x >> 5);
    if (q >= N) return;
    const float INF = __int_as_float(0x7F800000);

    // Local top-5 of this lane's ~6 strided values (sorted ascending)
    const float* p = g_partial + (size_t)q * PSTRIDE;
    float t[5] = {INF, INF, INF, INF, INF};
    #pragma unroll
    for (int j = 0; j < 6; j++) {
        int i = lane + j * 32;
        float v = (i < PSTRIDE) ? p[i] : INF;
        top5_update(t, v);
    }

    const float x2q = g_x2[q];
    const float mn  = *minv;
    const float inv = 1.0f / (*maxv - mn);

    int idx = 0;
    float sum = 0.0f;
    #pragma unroll
    for (int k = 0; k < KNN; k++) {
        float h = (idx == 0) ? t[0] : (idx == 1) ? t[1] : (idx == 2) ? t[2]
                : (idx == 3) ? t[3] : (idx == 4) ? t[4] : INF;
        float m = h;
        #pragma unroll
        for (int o = 16; o; o >>= 1) m = fminf(m, __shfl_xor_sync(0xFFFFFFFFu, m, o));
        unsigned ball = __ballot_sync(0xFFFFFFFFu, h == m);
        int src = __ffs(ball) - 1;
        if (lane == src) idx++;
        float d = sqrtf(fmaxf(x2q + m, 0.0f));
        sum += (d - mn) * inv;
    }
    if (lane == 0) out[q] = sum * (1.0f / KNN);
}

// ---------------------------------------------------------------------------
// Launch
// ---------------------------------------------------------------------------
extern "C" void kernel_launch(void* const* d_in, const int* in_sizes, int n_in,
                              void* d_out, int out_size) {
    const float* features = (const float*)d_in[0];
    const float* bank     = (const float*)d_in[1];
    const float* minv     = (const float*)d_in[2];
    const float* maxv     = (const float*)d_in[3];
    (void)n_in;

    const int N = in_sizes[0] / D_DIM;         // 2048
    const int M = in_sizes[1] / D_DIM;         // 100000
    const int TILES = (M + CB - 1) / CB;       // 782
    const int Mpad = TILES * CB;

    cudaFuncSetAttribute(knn_main, cudaFuncAttributeMaxDynamicSharedMemorySize,
                         SMEM_TOTAL);

    prep_bank<<<(Mpad + 7) / 8, 256>>>(bank, M, Mpad);
    prep_feat<<<(N + 7) / 8, 256>>>(features, N);
    knn_main<<<dim3(N / QB, NSPLIT), 512, SMEM_TOTAL>>>(features, TILES);
    knn_merge<<<(N + 7) / 8, 256>>>((float*)d_out, minv, maxv, N);
    (void)out_size;
}